// round 9
// baseline (speedup 1.0000x reference)
#include <cuda_runtime.h>
#include <math.h>

// Problem constants
constexpr int FH   = 96;
constexpr int FW   = 96;
constexpr int FC   = 512;
constexpr int FB   = 16;
constexpr int NROI = 32;
constexpr int NREG = 50;          // 1 + 4 + 9 + 36
constexpr int C4   = FC / 4;      // 128 float4 channels

constexpr int NTASK = 20;         // 6 (P6) + 6 (P3 bands x2) + 8 (P2 bands x4)

// Region table: per (roi, region) -> x1, x2, y1, y2
__device__ int4 d_regions[NROI * NREG];

// ---------------------------------------------------------------------------
// Exact Python-double region boundaries (identical to PASSING R1/R4/R7/R8).
// ---------------------------------------------------------------------------
__global__ void compute_regions_kernel(const int* __restrict__ rois) {
    int r = blockIdx.x * blockDim.x + threadIdx.x;
    if (r >= NROI * NREG) return;

    int roi = r / NREG;
    int k   = r % NREG;

    int P, off;
    if      (k < 1)  { P = 1; off = 0; }
    else if (k < 5)  { P = 2; off = 1; }
    else if (k < 14) { P = 3; off = 5; }
    else             { P = 6; off = 14; }
    int idx = k - off;
    int ix  = idx / P;
    int jy  = idx % P;

    double x = (double)rois[roi * 4 + 0];
    double y = (double)rois[roi * 4 + 1];
    double w = (double)rois[roi * 4 + 2];
    double h = (double)rois[roi * 4 + 3];

    double cl = h / (double)P;   // x-axis step (reference quirk)
    double rl = w / (double)P;   // y-axis step

    double tx = __dadd_rn(x, __dmul_rn((double)ix, cl));
    int x1 = (int)rint(tx);
    int x2 = (int)rint(__dadd_rn(tx, cl));

    double ty = __dadd_rn(y, __dmul_rn((double)jy, rl));
    int y1 = (int)rint(ty);
    int y2 = (int)rint(__dadd_rn(ty, rl));

    x1 = max(0, min(FW, x1));
    x2 = max(0, min(FW, x2));
    y1 = max(0, min(FH, y1));
    y2 = max(0, min(FH, y2));

    d_regions[r] = make_int4(x1, x2, y1, y2);
}

// Sign-split float atomic max on raw bits (proven in R6/R7/R8, rel_err=0).
__device__ __forceinline__ void atomicMaxFloat(float* addr, float v) {
    if (v >= 0.0f) atomicMax((int*)addr, __float_as_int(v));
    else           atomicMin((unsigned int*)addr, __float_as_uint(v));
}

// Init ONLY regions 0..13 (pool1/2/3) per (b, roi): pool6 is direct-stored.
__global__ void init_out14_kernel(unsigned int* __restrict__ out) {
    int i = blockIdx.x * blockDim.x + threadIdx.x;          // uint4 index
    int per = 14 * 128;                                     // uint4 per (b,roi)
    if (i >= FB * NROI * per) return;
    int pr = i / per;
    int k  = i % per;
    ((uint4*)out)[(size_t)pr * NREG * 128 + k] =
        make_uint4(0xFF800000u, 0xFF800000u, 0xFF800000u, 0xFF800000u);
}

__device__ __forceinline__ void vmax4(float4& a, const float4 b) {
    a.x = fmaxf(a.x, b.x);
    a.y = fmaxf(a.y, b.y);
    a.z = fmaxf(a.z, b.z);
    a.w = fmaxf(a.w, b.w);
}

// ---------------------------------------------------------------------------
// Band compute for pool level P at region offset OFF (unchanged from R8).
// ---------------------------------------------------------------------------
template <int P, int OFF, bool DIRECT>
__device__ __forceinline__ void band_compute(const float4* __restrict__ fmb,
                                             const int4*  __restrict__ regs,
                                             float*       __restrict__ outb,
                                             int j, int ys, int ye) {
    const float4 NEG = make_float4(-INFINITY, -INFINITY, -INFINITY, -INFINITY);
#pragma unroll
    for (int i = 0; i < P; i++) {
        int4 ri = __ldg(&regs[OFF + i * P]);     // x-range depends only on i
        int x1 = ri.x, x2 = ri.y;

        float4 a0 = NEG, a1 = NEG;
        for (int y = ys; y < ye; y++) {
            const float4* row = fmb + (size_t)y * (FW * C4);
            int x = x1;
            for (; x + 4 <= x2; x += 4) {
                vmax4(a0, __ldg(row + (size_t)x * C4));
                vmax4(a1, __ldg(row + (size_t)(x + 1) * C4));
                vmax4(a0, __ldg(row + (size_t)(x + 2) * C4));
                vmax4(a1, __ldg(row + (size_t)(x + 3) * C4));
            }
            for (; x < x2; x++)
                vmax4(a0, __ldg(row + (size_t)x * C4));
        }
        vmax4(a0, a1);

        float* o = outb + ((size_t)(OFF + i * P + j) << 9);
        if (DIRECT) {
            *(float4*)o = a0;
        } else {
            atomicMaxFloat(o + 0, a0.x);
            atomicMaxFloat(o + 1, a0.y);
            atomicMaxFloat(o + 2, a0.z);
            atomicMaxFloat(o + 3, a0.w);
        }
    }
}

// ---------------------------------------------------------------------------
// One block = (batch, roi, task). Band-aligned tasks (same as R8).
// __launch_bounds__(128, 12): cap regs at 42 -> 12 blocks/SM (75% occupancy
// ceiling) to hide L2 latency; R4-R8 were reg-limited to ~6 blocks/SM.
// ---------------------------------------------------------------------------
__global__ void __launch_bounds__(128, 12)
roi_pool_band(const float* __restrict__ fm, float* __restrict__ out) {
    int bid  = blockIdx.x;
    int task = bid % NTASK;
    int rr   = bid / NTASK;
    int roi  = rr & 31;
    int b    = rr >> 5;
    int c    = threadIdx.x;       // float4-channel 0..127

    const int4*   regs = d_regions + roi * NREG;
    const float4* fmb  = (const float4*)fm + (size_t)b * FH * FW * C4 + c;
    float*        outb = out + (((size_t)(b * NROI + roi) * NREG) << 9) + c * 4;

    if (task < 6) {
        int j = task;
        int4 rj = __ldg(&regs[14 + j]);           // band j exact y-range
        band_compute<6, 14, true>(fmb, regs, outb, j, rj.z, rj.w);
    } else if (task < 12) {
        int t = task - 6;
        int j = t >> 1, hf = t & 1;
        int4 rj = __ldg(&regs[5 + j]);
        int hgt = rj.w - rj.z;
        int ys = rj.z + (hgt * hf)     / 2;
        int ye = rj.z + (hgt * (hf+1)) / 2;
        band_compute<3, 5, false>(fmb, regs, outb, j, ys, ye);
    } else {
        int t = task - 12;
        int j = t >> 2, q = t & 3;
        int4 rj = __ldg(&regs[1 + j]);
        int hgt = rj.w - rj.z;
        int ys = rj.z + (hgt * q)     / 4;
        int ye = rj.z + (hgt * (q+1)) / 4;
        band_compute<2, 1, false>(fmb, regs, outb, j, ys, ye);
    }
}

// pool1 = max over pool2's 4 regions (bit-exact fold; validated rel_err=0).
__global__ void __launch_bounds__(256)
pool1_fold_kernel(float* __restrict__ out) {
    int t = blockIdx.x * blockDim.x + threadIdx.x;
    if (t >= FB * NROI * C4) return;
    int c4 = t & 127;
    int pr = t >> 7;              // b*32 + roi

    float4* base = (float4*)out + ((size_t)pr * NREG) * C4 + c4;
    float4 f0 = base[1 * C4];
    float4 f1 = base[2 * C4];
    float4 f2 = base[3 * C4];
    float4 f3 = base[4 * C4];
    vmax4(f0, f1);
    vmax4(f2, f3);
    vmax4(f0, f2);
    base[0] = f0;
}

extern "C" void kernel_launch(void* const* d_in, const int* in_sizes, int n_in,
                              void* d_out, int out_size) {
    const float* fm   = (const float*)d_in[0];
    const int*   rois = (const int*)d_in[1];
    float*       out  = (float*)d_out;

    compute_regions_kernel<<<(NROI * NREG + 255) / 256, 256>>>(rois);
    int ninit4 = FB * NROI * 14 * 128;            // uint4 count for regions 0..13
    init_out14_kernel<<<(ninit4 + 255) / 256, 256>>>((unsigned int*)out);
    roi_pool_band<<<FB * NROI * NTASK, 128>>>(fm, out);
    pool1_fold_kernel<<<(FB * NROI * C4 + 255) / 256, 256>>>(out);
}

// round 10
// speedup vs baseline: 1.4837x; 1.4837x over previous
#include <cuda_runtime.h>
#include <math.h>

// Problem constants
constexpr int FH   = 96;
constexpr int FW   = 96;
constexpr int FC   = 512;
constexpr int FB   = 16;
constexpr int NROI = 32;
constexpr int NREG = 50;          // 1 + 4 + 9 + 36
constexpr int C4   = FC / 4;      // 128 float4 channels
constexpr int RS   = FW * C4;     // row stride in float4 units

constexpr int NTASK = 20;         // 6 (P6) + 6 (P3 bands x2) + 8 (P2 bands x4)

// Region table: per (roi, region) -> x1, x2, y1, y2
__device__ int4 d_regions[NROI * NREG];

// ---------------------------------------------------------------------------
// Exact Python-double region boundaries (identical to PASSING R1/R4/R7/R8).
// ---------------------------------------------------------------------------
__global__ void compute_regions_kernel(const int* __restrict__ rois) {
    int r = blockIdx.x * blockDim.x + threadIdx.x;
    if (r >= NROI * NREG) return;

    int roi = r / NREG;
    int k   = r % NREG;

    int P, off;
    if      (k < 1)  { P = 1; off = 0; }
    else if (k < 5)  { P = 2; off = 1; }
    else if (k < 14) { P = 3; off = 5; }
    else             { P = 6; off = 14; }
    int idx = k - off;
    int ix  = idx / P;
    int jy  = idx % P;

    double x = (double)rois[roi * 4 + 0];
    double y = (double)rois[roi * 4 + 1];
    double w = (double)rois[roi * 4 + 2];
    double h = (double)rois[roi * 4 + 3];

    double cl = h / (double)P;   // x-axis step (reference quirk)
    double rl = w / (double)P;   // y-axis step

    double tx = __dadd_rn(x, __dmul_rn((double)ix, cl));
    int x1 = (int)rint(tx);
    int x2 = (int)rint(__dadd_rn(tx, cl));

    double ty = __dadd_rn(y, __dmul_rn((double)jy, rl));
    int y1 = (int)rint(ty);
    int y2 = (int)rint(__dadd_rn(ty, rl));

    x1 = max(0, min(FW, x1));
    x2 = max(0, min(FW, x2));
    y1 = max(0, min(FH, y1));
    y2 = max(0, min(FH, y2));

    d_regions[r] = make_int4(x1, x2, y1, y2);
}

// Sign-split float atomic max on raw bits (proven rel_err=0 in R6-R9).
__device__ __forceinline__ void atomicMaxFloat(float* addr, float v) {
    if (v >= 0.0f) atomicMax((int*)addr, __float_as_int(v));
    else           atomicMin((unsigned int*)addr, __float_as_uint(v));
}

// Init ONLY regions 0..13 (pool1/2/3) per (b, roi): pool6 is direct-stored.
__global__ void init_out14_kernel(unsigned int* __restrict__ out) {
    int i = blockIdx.x * blockDim.x + threadIdx.x;          // uint4 index
    int per = 14 * 128;                                     // uint4 per (b,roi)
    if (i >= FB * NROI * per) return;
    int pr = i / per;
    int k  = i % per;
    ((uint4*)out)[(size_t)pr * NREG * 128 + k] =
        make_uint4(0xFF800000u, 0xFF800000u, 0xFF800000u, 0xFF800000u);
}

__device__ __forceinline__ void vmax4(float4& a, const float4 b) {
    a.x = fmaxf(a.x, b.x);
    a.y = fmaxf(a.y, b.y);
    a.z = fmaxf(a.z, b.z);
    a.w = fmaxf(a.w, b.w);
}

// ---------------------------------------------------------------------------
// Band compute for pool level P at region offset OFF.
// Inner loop: 2 rows x 2 x-positions per iteration -> 4 independent loads in
// flight into 4 accumulators. y-pairing supplies MLP even for the narrow
// (6-10 px) pool6 segments where x-unrolling never kicked in (R8 weakness).
// ---------------------------------------------------------------------------
template <int P, int OFF, bool DIRECT>
__device__ __forceinline__ void band_compute(const float4* __restrict__ fmb,
                                             const int4*  __restrict__ regs,
                                             float*       __restrict__ outb,
                                             int j, int ys, int ye) {
    const float4 NEG = make_float4(-INFINITY, -INFINITY, -INFINITY, -INFINITY);
#pragma unroll
    for (int i = 0; i < P; i++) {
        int4 ri = __ldg(&regs[OFF + i * P]);     // x-range depends only on i
        int x1 = ri.x, x2 = ri.y;

        float4 a0 = NEG, a1 = NEG, a2 = NEG, a3 = NEG;

        int y = ys;
        for (; y + 2 <= ye; y += 2) {            // 2 rows concurrently
            const float4* r0 = fmb + (size_t)y * RS;
            const float4* r1 = r0 + RS;
            int x = x1;
            for (; x + 2 <= x2; x += 2) {        // x 2 x-positions = 4 loads
                vmax4(a0, __ldg(r0 + (size_t)x * C4));
                vmax4(a1, __ldg(r1 + (size_t)x * C4));
                vmax4(a2, __ldg(r0 + (size_t)(x + 1) * C4));
                vmax4(a3, __ldg(r1 + (size_t)(x + 1) * C4));
            }
            if (x < x2) {
                vmax4(a0, __ldg(r0 + (size_t)x * C4));
                vmax4(a1, __ldg(r1 + (size_t)x * C4));
            }
        }
        if (y < ye) {                            // trailing single row
            const float4* r0 = fmb + (size_t)y * RS;
            int x = x1;
            for (; x + 2 <= x2; x += 2) {
                vmax4(a0, __ldg(r0 + (size_t)x * C4));
                vmax4(a2, __ldg(r0 + (size_t)(x + 1) * C4));
            }
            if (x < x2)
                vmax4(a0, __ldg(r0 + (size_t)x * C4));
        }

        vmax4(a0, a1);
        vmax4(a2, a3);
        vmax4(a0, a2);

        float* o = outb + ((size_t)(OFF + i * P + j) << 9);
        if (DIRECT) {
            *(float4*)o = a0;
        } else {
            atomicMaxFloat(o + 0, a0.x);
            atomicMaxFloat(o + 1, a0.y);
            atomicMaxFloat(o + 2, a0.z);
            atomicMaxFloat(o + 3, a0.w);
        }
    }
}

// ---------------------------------------------------------------------------
// One block = (batch, roi, task). Band-aligned tasks (same as R8). Task is
// fastest-varying in bid -> the 3 pool levels of one (b, roi) are co-resident
// and re-hit the same lines in L2. NO occupancy cap (R9's cap spilled).
// ---------------------------------------------------------------------------
__global__ void __launch_bounds__(128)
roi_pool_band(const float* __restrict__ fm, float* __restrict__ out) {
    int bid  = blockIdx.x;
    int task = bid % NTASK;
    int rr   = bid / NTASK;
    int roi  = rr & 31;
    int b    = rr >> 5;
    int c    = threadIdx.x;       // float4-channel 0..127

    const int4*   regs = d_regions + roi * NREG;
    const float4* fmb  = (const float4*)fm + (size_t)b * FH * FW * C4 + c;
    float*        outb = out + (((size_t)(b * NROI + roi) * NREG) << 9) + c * 4;

    if (task < 6) {
        int j = task;
        int4 rj = __ldg(&regs[14 + j]);           // band j exact y-range
        band_compute<6, 14, true>(fmb, regs, outb, j, rj.z, rj.w);
    } else if (task < 12) {
        int t = task - 6;
        int j = t >> 1, hf = t & 1;
        int4 rj = __ldg(&regs[5 + j]);
        int hgt = rj.w - rj.z;
        int ys = rj.z + (hgt * hf)     / 2;
        int ye = rj.z + (hgt * (hf+1)) / 2;
        band_compute<3, 5, false>(fmb, regs, outb, j, ys, ye);
    } else {
        int t = task - 12;
        int j = t >> 2, q = t & 3;
        int4 rj = __ldg(&regs[1 + j]);
        int hgt = rj.w - rj.z;
        int ys = rj.z + (hgt * q)     / 4;
        int ye = rj.z + (hgt * (q+1)) / 4;
        band_compute<2, 1, false>(fmb, regs, outb, j, ys, ye);
    }
}

// pool1 = max over pool2's 4 regions (bit-exact fold; validated rel_err=0).
__global__ void __launch_bounds__(256)
pool1_fold_kernel(float* __restrict__ out) {
    int t = blockIdx.x * blockDim.x + threadIdx.x;
    if (t >= FB * NROI * C4) return;
    int c4 = t & 127;
    int pr = t >> 7;              // b*32 + roi

    float4* base = (float4*)out + ((size_t)pr * NREG) * C4 + c4;
    float4 f0 = base[1 * C4];
    float4 f1 = base[2 * C4];
    float4 f2 = base[3 * C4];
    float4 f3 = base[4 * C4];
    vmax4(f0, f1);
    vmax4(f2, f3);
    vmax4(f0, f2);
    base[0] = f0;
}

extern "C" void kernel_launch(void* const* d_in, const int* in_sizes, int n_in,
                              void* d_out, int out_size) {
    const float* fm   = (const float*)d_in[0];
    const int*   rois = (const int*)d_in[1];
    float*       out  = (float*)d_out;

    compute_regions_kernel<<<(NROI * NREG + 255) / 256, 256>>>(rois);
    int ninit4 = FB * NROI * 14 * 128;            // uint4 count for regions 0..13
    init_out14_kernel<<<(ninit4 + 255) / 256, 256>>>((unsigned int*)out);
    roi_pool_band<<<FB * NROI * NTASK, 128>>>(fm, out);
    pool1_fold_kernel<<<(FB * NROI * C4 + 255) / 256, 256>>>(out);
}

// round 11
// speedup vs baseline: 1.5250x; 1.0279x over previous
#include <cuda_runtime.h>
#include <math.h>

// Problem constants
constexpr int FH   = 96;
constexpr int FW   = 96;
constexpr int FC   = 512;
constexpr int FB   = 16;
constexpr int NROI = 32;
constexpr int NREG = 50;          // 1 + 4 + 9 + 36
constexpr int C4   = FC / 4;      // 128 float4 channels
constexpr int RS   = FW * C4;     // row stride in float4 units

constexpr int NTASK = 20;         // 6 (P6) + 6 (P3 bands x2) + 8 (P2 bands x4)

// Region table: per (roi, region) -> x1, x2, y1, y2
__device__ int4 d_regions[NROI * NREG];

// ---------------------------------------------------------------------------
// Prep kernel: init regions 0..13 of every (b,roi) to -inf AND compute the
// exact Python-double region boundaries (same verified math as R1/R4/R8/R10).
// ---------------------------------------------------------------------------
__global__ void prep_kernel(const int* __restrict__ rois,
                            unsigned int* __restrict__ out) {
    int gid = blockIdx.x * blockDim.x + threadIdx.x;

    // Part 1: init output regions 0..13 per (b, roi) to raw -inf bits.
    {
        constexpr int per = 14 * 128;                 // uint4 per (b,roi)
        if (gid < FB * NROI * per) {
            int pr = gid / per;
            int k  = gid % per;
            ((uint4*)out)[(size_t)pr * NREG * 128 + k] =
                make_uint4(0xFF800000u, 0xFF800000u, 0xFF800000u, 0xFF800000u);
        }
    }

    // Part 2: region boundary table (first 1600 threads).
    if (gid >= NROI * NREG) return;
    int roi = gid / NREG;
    int k   = gid % NREG;

    int P, off;
    if      (k < 1)  { P = 1; off = 0; }
    else if (k < 5)  { P = 2; off = 1; }
    else if (k < 14) { P = 3; off = 5; }
    else             { P = 6; off = 14; }
    int idx = k - off;
    int ix  = idx / P;
    int jy  = idx % P;

    double x = (double)rois[roi * 4 + 0];
    double y = (double)rois[roi * 4 + 1];
    double w = (double)rois[roi * 4 + 2];
    double h = (double)rois[roi * 4 + 3];

    double cl = h / (double)P;   // x-axis step (reference quirk)
    double rl = w / (double)P;   // y-axis step

    double tx = __dadd_rn(x, __dmul_rn((double)ix, cl));
    int x1 = (int)rint(tx);
    int x2 = (int)rint(__dadd_rn(tx, cl));

    double ty = __dadd_rn(y, __dmul_rn((double)jy, rl));
    int y1 = (int)rint(ty);
    int y2 = (int)rint(__dadd_rn(ty, rl));

    x1 = max(0, min(FW, x1));
    x2 = max(0, min(FW, x2));
    y1 = max(0, min(FH, y1));
    y2 = max(0, min(FH, y2));

    d_regions[roi * NREG + k] = make_int4(x1, x2, y1, y2);
}

// Sign-split float atomic max on raw bits (proven rel_err=0 in R6-R10).
__device__ __forceinline__ void atomicMaxFloat(float* addr, float v) {
    if (v >= 0.0f) atomicMax((int*)addr, __float_as_int(v));
    else           atomicMin((unsigned int*)addr, __float_as_uint(v));
}

__device__ __forceinline__ void vmax4(float4& a, const float4 b) {
    a.x = fmaxf(a.x, b.x);
    a.y = fmaxf(a.y, b.y);
    a.z = fmaxf(a.z, b.z);
    a.w = fmaxf(a.w, b.w);
}

__device__ __forceinline__ void atomic4(float* o, const float4 a) {
    atomicMaxFloat(o + 0, a.x);
    atomicMaxFloat(o + 1, a.y);
    atomicMaxFloat(o + 2, a.z);
    atomicMaxFloat(o + 3, a.w);
}

// ---------------------------------------------------------------------------
// Band compute for pool level P at region offset OFF.
// Inner tile: 2 rows x 4 x-positions = 8 loads batched into temps before any
// fmax -> 8 independent LDG.128 in flight per warp (R10 had 4).
// FOLD0: also atomically fold this partial into region 0 (pool1; exact
// because pool2's regions tile pool1's box — validated rel_err=0 since R7).
// ---------------------------------------------------------------------------
template <int P, int OFF, bool DIRECT, bool FOLD0>
__device__ __forceinline__ void band_compute(const float4* __restrict__ fmb,
                                             const int4*  __restrict__ regs,
                                             float*       __restrict__ outb,
                                             int j, int ys, int ye) {
    const float4 NEG = make_float4(-INFINITY, -INFINITY, -INFINITY, -INFINITY);
#pragma unroll
    for (int i = 0; i < P; i++) {
        int4 ri = __ldg(&regs[OFF + i * P]);     // x-range depends only on i
        int x1 = ri.x, x2 = ri.y;

        float4 a0 = NEG, a1 = NEG, a2 = NEG, a3 = NEG;

        int y = ys;
        for (; y + 2 <= ye; y += 2) {            // 2 rows concurrently
            const float4* r0 = fmb + (size_t)y * RS;
            const float4* r1 = r0 + RS;
            int x = x1;
            for (; x + 4 <= x2; x += 4) {        // x4 -> 8 loads in flight
                float4 v0 = __ldg(r0 + (size_t)x * C4);
                float4 v1 = __ldg(r1 + (size_t)x * C4);
                float4 v2 = __ldg(r0 + (size_t)(x + 1) * C4);
                float4 v3 = __ldg(r1 + (size_t)(x + 1) * C4);
                float4 v4 = __ldg(r0 + (size_t)(x + 2) * C4);
                float4 v5 = __ldg(r1 + (size_t)(x + 2) * C4);
                float4 v6 = __ldg(r0 + (size_t)(x + 3) * C4);
                float4 v7 = __ldg(r1 + (size_t)(x + 3) * C4);
                vmax4(a0, v0); vmax4(a1, v1);
                vmax4(a2, v2); vmax4(a3, v3);
                vmax4(a0, v4); vmax4(a1, v5);
                vmax4(a2, v6); vmax4(a3, v7);
            }
            for (; x < x2; x++) {                // 2-row remainder (MLP 2)
                float4 v0 = __ldg(r0 + (size_t)x * C4);
                float4 v1 = __ldg(r1 + (size_t)x * C4);
                vmax4(a0, v0); vmax4(a1, v1);
            }
        }
        if (y < ye) {                            // trailing single row
            const float4* r0 = fmb + (size_t)y * RS;
            int x = x1;
            for (; x + 2 <= x2; x += 2) {
                float4 v0 = __ldg(r0 + (size_t)x * C4);
                float4 v1 = __ldg(r0 + (size_t)(x + 1) * C4);
                vmax4(a0, v0); vmax4(a2, v1);
            }
            if (x < x2)
                vmax4(a0, __ldg(r0 + (size_t)x * C4));
        }

        vmax4(a0, a1);
        vmax4(a2, a3);
        vmax4(a0, a2);

        float* o = outb + ((size_t)(OFF + i * P + j) << 9);
        if (DIRECT) {
            *(float4*)o = a0;
        } else {
            atomic4(o, a0);
        }
        if (FOLD0) {
            atomic4(outb, a0);                   // pool1 (region 0) fold
        }
    }
}

// ---------------------------------------------------------------------------
// One block = (batch, roi, task). Band-aligned tasks (unchanged from R8/R10).
// ---------------------------------------------------------------------------
__global__ void __launch_bounds__(128)
roi_pool_band(const float* __restrict__ fm, float* __restrict__ out) {
    int bid  = blockIdx.x;
    int task = bid % NTASK;
    int rr   = bid / NTASK;
    int roi  = rr & 31;
    int b    = rr >> 5;
    int c    = threadIdx.x;       // float4-channel 0..127

    const int4*   regs = d_regions + roi * NREG;
    const float4* fmb  = (const float4*)fm + (size_t)b * FH * FW * C4 + c;
    float*        outb = out + (((size_t)(b * NROI + roi) * NREG) << 9) + c * 4;

    if (task < 6) {
        int j = task;
        int4 rj = __ldg(&regs[14 + j]);           // band j exact y-range
        band_compute<6, 14, true, false>(fmb, regs, outb, j, rj.z, rj.w);
    } else if (task < 12) {
        int t = task - 6;
        int j = t >> 1, hf = t & 1;
        int4 rj = __ldg(&regs[5 + j]);
        int hgt = rj.w - rj.z;
        int ys = rj.z + (hgt * hf)     / 2;
        int ye = rj.z + (hgt * (hf+1)) / 2;
        band_compute<3, 5, false, false>(fmb, regs, outb, j, ys, ye);
    } else {
        int t = task - 12;
        int j = t >> 2, q = t & 3;
        int4 rj = __ldg(&regs[1 + j]);
        int hgt = rj.w - rj.z;
        int ys = rj.z + (hgt * q)     / 4;
        int ye = rj.z + (hgt * (q+1)) / 4;
        band_compute<2, 1, false, true>(fmb, regs, outb, j, ys, ye);
    }
}

extern "C" void kernel_launch(void* const* d_in, const int* in_sizes, int n_in,
                              void* d_out, int out_size) {
    const float* fm   = (const float*)d_in[0];
    const int*   rois = (const int*)d_in[1];
    float*       out  = (float*)d_out;

    int ninit4 = FB * NROI * 14 * 128;            // uint4 count for regions 0..13
    prep_kernel<<<(ninit4 + 255) / 256, 256>>>(rois, (unsigned int*)out);
    roi_pool_band<<<FB * NROI * NTASK, 128>>>(fm, out);
}